// round 9
// baseline (speedup 1.0000x reference)
#include <cuda_runtime.h>
#include <cuda_bf16.h>

// ============================================================================
// QLSTM  (SEQ=2048, B=64, D=512, H=512)
//
// Inputs (metadata order): inputs[2048,64,512], Wf[512,1024], bf[512],
//                          Wi, bi, Wg, bg, Wo, bo
// Output: outputs[2048,64,512] ++ hx[64,512] ++ cx[64,512]  (float32)
//
// Phase 0: pack weights:
//   g_Wpack[k][n]  (k<512, n=4j+g)  = W_g[j][k]        (input half, K-major-T)
//   g_Whp  [n][k]                   = W_g[j][512+k]    (hidden half, row-major)
//   g_bpack[n]                      = b_g[j]
// Phase 1: SGEMM  Gx[m][n] = x[m][:512] . Wpack[:, n] + bpack[n],  m = t*64+b
// Phase 2: persistent LSTM kernel, 128 CTAs, grid barrier per step.
// ============================================================================

typedef unsigned long long ull;

#define SEQ   2048
#define BATCH 64
#define DIN   512
#define HID   512
#define NGATE 2048              // 4*HID, gate-rows
#define M_TOT (SEQ * BATCH)     // 131072

// ---- device scratch (static __device__ = sanctioned no-alloc scratch) ------
__device__ float g_Gx[(size_t)M_TOT * NGATE];     // 1 GiB gate pre-activations
__device__ float g_Wpack[DIN * NGATE];            // 4 MiB  [k][n]
__device__ float g_Whp[NGATE * HID];              // 4 MiB  [n][k]
__device__ float g_bpack[NGATE];
__device__ float g_hT[2 * HID * BATCH];           // double-buffered h, [k][b]
__device__ unsigned g_arrive[128];                // barrier arrival slots
__device__ unsigned g_bar_gen;                    // barrier generation

// ---- f32x2 helpers (FFMA2: PTX-only, sm_100+) ------------------------------
__device__ __forceinline__ void ffma2(ull& d, ull a, ull b) {
    asm("fma.rn.f32x2 %0, %1, %2, %0;" : "+l"(d) : "l"(a), "l"(b));
}
__device__ __forceinline__ ull pack2(float x) {
    ull r; asm("mov.b64 %0, {%1, %1};" : "=l"(r) : "f"(x)); return r;
}
__device__ __forceinline__ void unpack2(ull v, float& lo, float& hi) {
    asm("mov.b64 {%0, %1}, %2;" : "=f"(lo), "=f"(hi) : "l"(v));
}

// ---- fast, accurate-enough activations (rel err ~1e-6) ---------------------
__device__ __forceinline__ float sigmoidf_(float x) {
    return __fdividef(1.0f, 1.0f + __expf(-x));
}
__device__ __forceinline__ float tanhf_(float x) {
    return 1.0f - __fdividef(2.0f, __expf(2.0f * x) + 1.0f);
}

// ============================================================================
// Phase 0a: reset barrier state (stream-ordered; runs before the seq kernel)
// ============================================================================
__global__ void qlstm_reset() {
    int t = threadIdx.x;
    if (t < 128) g_arrive[t] = 0u;
    if (t == 0)  g_bar_gen = 0u;
}

// ============================================================================
// Phase 0b: pack weights/biases
// ============================================================================
__global__ void qlstm_pack(const float* __restrict__ Wf, const float* __restrict__ bf,
                           const float* __restrict__ Wi, const float* __restrict__ bi,
                           const float* __restrict__ Wg, const float* __restrict__ bg,
                           const float* __restrict__ Wo, const float* __restrict__ bo) {
    const float* Ws[4] = {Wf, Wi, Wg, Wo};
    const float* bs[4] = {bf, bi, bg, bo};
    const int stride = gridDim.x * blockDim.x;
    const int idx = blockIdx.x * blockDim.x + threadIdx.x;

    // g_Wpack[k][n] = W_g[j][k]
    for (int i = idx; i < DIN * NGATE; i += stride) {
        int n = i & (NGATE - 1);
        int k = i >> 11;                 // / NGATE
        int j = n >> 2, g = n & 3;
        g_Wpack[i] = Ws[g][j * (DIN + HID) + k];
    }
    // g_Whp[n][k] = W_g[j][512+k]
    for (int i = idx; i < NGATE * HID; i += stride) {
        int k = i & (HID - 1);
        int n = i >> 9;                  // / HID
        int j = n >> 2, g = n & 3;
        g_Whp[i] = Ws[g][j * (DIN + HID) + DIN + k];
    }
    for (int i = idx; i < NGATE; i += stride) {
        int j = i >> 2, g = i & 3;
        g_bpack[i] = bs[g][j];
    }
}

// ============================================================================
// Phase 1: SGEMM  g_Gx[m][n] = A[m][:] . g_Wpack[:, n] + g_bpack[n]
// 128x128x16 tiles, 256 threads, 8x8 microtile, f32x2 FFMA2 (n-paired).
// ============================================================================
__global__ void __launch_bounds__(256, 1)
qlstm_gemm_x(const float* __restrict__ A) {
    __shared__ float As[16][132];        // [k][m], padded (2-way store conflicts ok)
    __shared__ float Bs[16][128];        // [k][n]

    const int tid = threadIdx.x;
    const int n0 = blockIdx.x * 128;
    const int m0 = blockIdx.y * 128;
    const int tn = (tid & 15) * 8;
    const int tm = (tid >> 4) * 8;
    const int a_k = (tid & 3) * 4;       // k-quad base 0/4/8/12
    const int a_m = tid >> 2;            // 0..63  (rows a_m, a_m+64)
    const int b_n = (tid & 31) * 4;      // n-quad
    const int b_k = tid >> 5;            // 0..7   (rows b_k, b_k+8)

    ull acc[8][4];
#pragma unroll
    for (int i = 0; i < 8; i++)
#pragma unroll
        for (int j = 0; j < 4; j++) acc[i][j] = 0ull;

    for (int k0 = 0; k0 < DIN; k0 += 16) {
#pragma unroll
        for (int r = 0; r < 2; r++) {
            int m = a_m + r * 64;
            float4 v = *(const float4*)(A + (size_t)(m0 + m) * DIN + k0 + a_k);
            As[a_k + 0][m] = v.x; As[a_k + 1][m] = v.y;
            As[a_k + 2][m] = v.z; As[a_k + 3][m] = v.w;
        }
#pragma unroll
        for (int r = 0; r < 2; r++) {
            int kk = b_k + r * 8;
            *(float4*)&Bs[kk][b_n] =
                *(const float4*)(g_Wpack + (size_t)(k0 + kk) * NGATE + n0 + b_n);
        }
        __syncthreads();
#pragma unroll
        for (int kk = 0; kk < 16; kk++) {
            float a0[8];
#pragma unroll
            for (int i = 0; i < 8; i += 4) {
                float4 v = *(const float4*)&As[kk][tm + i];
                a0[i] = v.x; a0[i + 1] = v.y; a0[i + 2] = v.z; a0[i + 3] = v.w;
            }
            ull bp[4];
#pragma unroll
            for (int j = 0; j < 4; j++)
                bp[j] = *(const ull*)&Bs[kk][tn + 2 * j];   // b64 LDS -> f32x2 pair
#pragma unroll
            for (int i = 0; i < 8; i++) {
                ull ap = pack2(a0[i]);
#pragma unroll
                for (int j = 0; j < 4; j++) ffma2(acc[i][j], ap, bp[j]);
            }
        }
        __syncthreads();
    }

    // epilogue: + bias, store float4 pairs
    float bn_[8];
#pragma unroll
    for (int j = 0; j < 8; j++) bn_[j] = g_bpack[n0 + tn + j];
#pragma unroll
    for (int i = 0; i < 8; i++) {
        float o[8];
#pragma unroll
        for (int j = 0; j < 4; j++) unpack2(acc[i][j], o[2 * j], o[2 * j + 1]);
#pragma unroll
        for (int j = 0; j < 8; j++) o[j] += bn_[j];
        size_t base = (size_t)(m0 + tm + i) * NGATE + n0 + tn;
        *(float4*)(g_Gx + base)     = make_float4(o[0], o[1], o[2], o[3]);
        *(float4*)(g_Gx + base + 4) = make_float4(o[4], o[5], o[6], o[7]);
    }
}

// ============================================================================
// Phase 2: persistent sequential LSTM.  128 CTAs x 256 threads.
//   CTA c owns gate-rows [16c, 16c+16) == hidden cells [4c, 4c+4).
//   GEMM map: warp rp -> rows {2rp,2rp+1}; lane: kh=lane>>4 (k half),
//             bq=lane&15 -> batches {2bq,2bq+1, 32+2bq,33+2bq} (conflict-free
//             LDS.64 pairs straight into f32x2 operands).
//   Elementwise map: thread -> (cell jl=tid>>6, batch b=tid&63); c in regs.
//   h exchanged via double-buffered global g_hT[k][b]; flag-array grid barrier.
// ============================================================================
__device__ __forceinline__ void grid_bar(int target) {
    __threadfence();
    __syncthreads();
    if (blockIdx.x == 0) {
        int t = threadIdx.x;
        if (t >= 1 && t < 128) {
            while (((volatile unsigned*)g_arrive)[t] < (unsigned)target) {}
        }
        __syncthreads();
        if (t == 0) {
            __threadfence();
            *((volatile unsigned*)&g_bar_gen) = (unsigned)target;
        }
    } else {
        if (threadIdx.x == 0) {
            ((volatile unsigned*)g_arrive)[blockIdx.x] = (unsigned)target;
            while (*((volatile unsigned*)&g_bar_gen) < (unsigned)target) {}
        }
    }
    __syncthreads();
    __threadfence();
}

__global__ void __launch_bounds__(256, 1)
qlstm_seq(float* __restrict__ out) {
    extern __shared__ float sm[];
    float* sWh = sm;                               // [16][512]  32 KB
    float* sH  = sm + 16 * HID;                    // [512][64] 128 KB
    float* sG  = sm + 16 * HID + HID * BATCH;      // [16][64]    4 KB

    const int tid = threadIdx.x;
    const int cta = blockIdx.x;
    const int n0 = cta * 16;

    // resident Wh slice (reused for all 2048 steps)
    for (int i = tid; i < 16 * HID / 4; i += 256)
        ((float4*)sWh)[i] = ((const float4*)(g_Whp + (size_t)n0 * HID))[i];

    const int rp   = tid >> 5;
    const int lane = tid & 31;
    const int kh   = lane >> 4;        // 0/1: k in [kh*256, kh*256+256)
    const int bq   = lane & 15;
    const int kbase = kh * 256;
    const float* wr0 = sWh + (2 * rp) * HID;
    const float* wr1 = wr0 + HID;
    const int bl = 2 * bq;             // low batch pair
    const int bh = 32 + 2 * bq;        // high batch pair

    const int jl = tid >> 6;           // cell within CTA, 0..3
    const int b  = tid & 63;           // batch
    const int jg = cta * 4 + jl;       // global hidden index
    float c_state = 0.0f, h_val = 0.0f;

    __syncthreads();

    for (int t = 0; t < SEQ; t++) {
        // prefetch Gx early (independent of h) to hide the uncoalesced latency
        float4 gx = *(const float4*)(g_Gx + (size_t)(t * BATCH + b) * NGATE + n0 + jl * 4);
        float4 pre;

        if (t > 0) {
            const float* src = g_hT + ((t - 1) & 1) * (HID * BATCH);
            for (int i = tid; i < HID * BATCH / 4; i += 256)
                ((float4*)sH)[i] = ((const float4*)src)[i];
            __syncthreads();

            ull a00 = 0, a01 = 0, a10 = 0, a11 = 0;
            for (int kk = 0; kk < 256; kk += 4) {
                const int k = kbase + kk;
                float4 w0v = *(const float4*)(wr0 + k);
                float4 w1v = *(const float4*)(wr1 + k);
                float w0a[4] = {w0v.x, w0v.y, w0v.z, w0v.w};
                float w1a[4] = {w1v.x, w1v.y, w1v.z, w1v.w};
#pragma unroll
                for (int u = 0; u < 4; u++) {
                    const float* hr = sH + (k + u) * BATCH;
                    ull hp0 = *(const ull*)(hr + bl);    // (h[bl], h[bl+1])
                    ull hp1 = *(const ull*)(hr + bh);    // (h[bh], h[bh+1])
                    ull wp0 = pack2(w0a[u]);
                    ull wp1 = pack2(w1a[u]);
                    ffma2(a00, wp0, hp0); ffma2(a01, wp0, hp1);
                    ffma2(a10, wp1, hp0); ffma2(a11, wp1, hp1);
                }
            }
            float s[8];
            unpack2(a00, s[0], s[1]); unpack2(a01, s[2], s[3]);
            unpack2(a10, s[4], s[5]); unpack2(a11, s[6], s[7]);
#pragma unroll
            for (int i = 0; i < 8; i++)
                s[i] += __shfl_xor_sync(0xffffffffu, s[i], 16);  // k-half partner
            if (kh == 0) {
                *(float2*)&sG[(2 * rp) * BATCH + bl]     = make_float2(s[0], s[1]);
                *(float2*)&sG[(2 * rp) * BATCH + bh]     = make_float2(s[2], s[3]);
                *(float2*)&sG[(2 * rp + 1) * BATCH + bl] = make_float2(s[4], s[5]);
                *(float2*)&sG[(2 * rp + 1) * BATCH + bh] = make_float2(s[6], s[7]);
            }
            __syncthreads();
            pre.x = gx.x + sG[(jl * 4 + 0) * BATCH + b];
            pre.y = gx.y + sG[(jl * 4 + 1) * BATCH + b];
            pre.z = gx.z + sG[(jl * 4 + 2) * BATCH + b];
            pre.w = gx.w + sG[(jl * 4 + 3) * BATCH + b];
        } else {
            pre = gx;                   // h0 = 0: hidden contribution is zero
        }

        float fg = sigmoidf_(pre.x);
        float ig = sigmoidf_(pre.y);
        float gg = tanhf_(pre.z);
        float og = sigmoidf_(pre.w);
        c_state = fg * c_state + ig * gg;
        h_val = og * tanhf_(c_state);

        out[(size_t)(t * BATCH + b) * HID + jg] = h_val;               // outputs
        g_hT[(t & 1) * (HID * BATCH) + jg * BATCH + b] = h_val;        // hT[k][b]

        grid_bar(t + 1);
    }

    const size_t off = (size_t)SEQ * BATCH * HID;
    out[off + (size_t)b * HID + jg] = h_val;                            // hx
    out[off + (size_t)BATCH * HID + (size_t)b * HID + jg] = c_state;    // cx
}

// ============================================================================
// Launch
// ============================================================================
extern "C" void kernel_launch(void* const* d_in, const int* in_sizes, int n_in,
                              void* d_out, int out_size) {
    const float* x  = (const float*)d_in[0];
    const float* Wf = (const float*)d_in[1];
    const float* bf = (const float*)d_in[2];
    const float* Wi = (const float*)d_in[3];
    const float* bi = (const float*)d_in[4];
    const float* Wg = (const float*)d_in[5];
    const float* bg = (const float*)d_in[6];
    const float* Wo = (const float*)d_in[7];
    const float* bo = (const float*)d_in[8];
    float* out = (float*)d_out;

    qlstm_reset<<<1, 128>>>();
    qlstm_pack<<<256, 256>>>(Wf, bf, Wi, bi, Wg, bg, Wo, bo);

    dim3 g1(NGATE / 128, M_TOT / 128);   // (16, 1024)
    qlstm_gemm_x<<<g1, 256>>>(x);

    const int smem_bytes = (16 * HID + HID * BATCH + 16 * BATCH) * 4;  // 167936
    cudaFuncSetAttribute(qlstm_seq, cudaFuncAttributeMaxDynamicSharedMemorySize,
                         smem_bytes);
    qlstm_seq<<<128, 256, smem_bytes>>>(out);
}

// round 10
// speedup vs baseline: 1.0536x; 1.0536x over previous
#include <cuda_runtime.h>
#include <cuda_bf16.h>

// ============================================================================
// QLSTM  (SEQ=2048, B=64, D=512, H=512)
// Phase 0: pack weights (Wpack [k][n] for phase1, Whp [n][k] for phase2)
// Phase 1: SGEMM Gx = x @ Wx^T + b, stored in phase2-friendly layout
//          g_Gx[t][cta(128)][b(64)][16 local gates]
// Phase 2: persistent kernel, 128 CTAs, 1/SM, counter grid-barrier per step.
//          Per CTA: 16 gate rows resident in smem as duplicated f32x2 pairs;
//          8 rows/warp x 4-way k-split; h staged in smem per step.
// ============================================================================

typedef unsigned long long ull;

#define SEQ   2048
#define BATCH 64
#define DIN   512
#define HID   512
#define NGATE 2048
#define M_TOT (SEQ * BATCH)

// ---- device scratch --------------------------------------------------------
__device__ float g_Gx[(size_t)M_TOT * NGATE];     // 1 GiB, [t][cta][b][16]
__device__ float g_Wpack[DIN * NGATE];            // [k][n], n = 4j+g
__device__ float g_Whp[NGATE * HID];              // [n][k]
__device__ float g_bpack[NGATE];
__device__ float g_hT[2 * HID * BATCH];           // double-buffered h, [jg][b]
__device__ unsigned g_bar;                        // grid barrier counter

// ---- f32x2 helpers ---------------------------------------------------------
__device__ __forceinline__ void ffma2(ull& d, ull a, ull b) {
    asm("fma.rn.f32x2 %0, %1, %2, %0;" : "+l"(d) : "l"(a), "l"(b));
}
__device__ __forceinline__ ull pack2(float x) {
    ull r; asm("mov.b64 %0, {%1, %1};" : "=l"(r) : "f"(x)); return r;
}
__device__ __forceinline__ void unpack2(ull v, float& lo, float& hi) {
    asm("mov.b64 {%0, %1}, %2;" : "=f"(lo), "=f"(hi) : "l"(v));
}

__device__ __forceinline__ float sigmoidf_(float x) {
    return __fdividef(1.0f, 1.0f + __expf(-x));
}
__device__ __forceinline__ float tanhf_(float x) {
    return 1.0f - __fdividef(2.0f, __expf(2.0f * x) + 1.0f);
}

// ============================================================================
__global__ void qlstm_reset() {
    if (threadIdx.x == 0) g_bar = 0u;
}

// ============================================================================
__global__ void qlstm_pack(const float* __restrict__ Wf, const float* __restrict__ bf,
                           const float* __restrict__ Wi, const float* __restrict__ bi,
                           const float* __restrict__ Wg, const float* __restrict__ bg,
                           const float* __restrict__ Wo, const float* __restrict__ bo) {
    const float* Ws[4] = {Wf, Wi, Wg, Wo};
    const float* bs[4] = {bf, bi, bg, bo};
    const int stride = gridDim.x * blockDim.x;
    const int idx = blockIdx.x * blockDim.x + threadIdx.x;

    for (int i = idx; i < DIN * NGATE; i += stride) {       // Wpack[k][n]
        int n = i & (NGATE - 1);
        int k = i >> 11;
        int j = n >> 2, g = n & 3;
        g_Wpack[i] = Ws[g][j * (DIN + HID) + k];
    }
    for (int i = idx; i < NGATE * HID; i += stride) {       // Whp[n][k]
        int k = i & (HID - 1);
        int n = i >> 9;
        int j = n >> 2, g = n & 3;
        g_Whp[i] = Ws[g][j * (DIN + HID) + DIN + k];
    }
    for (int i = idx; i < NGATE; i += stride) {
        int j = i >> 2, g = i & 3;
        g_bpack[i] = bs[g][j];
    }
}

// ============================================================================
// Phase 1: SGEMM with register prefetch of the next k-tile.
// 128x128x16 tiles, 256 threads, 8x8 microtile, FFMA2.
// ============================================================================
__global__ void __launch_bounds__(256, 1)
qlstm_gemm_x(const float* __restrict__ A) {
    __shared__ float As[16][132];
    __shared__ float Bs[16][128];

    const int tid = threadIdx.x;
    const int n0 = blockIdx.x * 128;
    const int m0 = blockIdx.y * 128;
    const int tn = (tid & 15) * 8;
    const int tm = (tid >> 4) * 8;
    const int a_k = (tid & 3) * 4;
    const int a_m = tid >> 2;
    const int b_n = (tid & 31) * 4;
    const int b_k = tid >> 5;

    ull acc[8][4];
#pragma unroll
    for (int i = 0; i < 8; i++)
#pragma unroll
        for (int j = 0; j < 4; j++) acc[i][j] = 0ull;

    float4 pa[2], pb[2];
#pragma unroll
    for (int r = 0; r < 2; r++) {
        pa[r] = *(const float4*)(A + (size_t)(m0 + a_m + r * 64) * DIN + a_k);
        pb[r] = *(const float4*)(g_Wpack + (size_t)(b_k + r * 8) * NGATE + n0 + b_n);
    }

    for (int k0 = 0; k0 < DIN; k0 += 16) {
#pragma unroll
        for (int r = 0; r < 2; r++) {
            int m = a_m + r * 64;
            As[a_k + 0][m] = pa[r].x; As[a_k + 1][m] = pa[r].y;
            As[a_k + 2][m] = pa[r].z; As[a_k + 3][m] = pa[r].w;
            *(float4*)&Bs[b_k + r * 8][b_n] = pb[r];
        }
        __syncthreads();

        if (k0 + 16 < DIN) {                 // prefetch next tile (hides LDG)
#pragma unroll
            for (int r = 0; r < 2; r++) {
                pa[r] = *(const float4*)(A + (size_t)(m0 + a_m + r * 64) * DIN + k0 + 16 + a_k);
                pb[r] = *(const float4*)(g_Wpack + (size_t)(k0 + 16 + b_k + r * 8) * NGATE + n0 + b_n);
            }
        }
#pragma unroll
        for (int kk = 0; kk < 16; kk++) {
            float a0[8];
#pragma unroll
            for (int i = 0; i < 8; i += 4) {
                float4 v = *(const float4*)&As[kk][tm + i];
                a0[i] = v.x; a0[i + 1] = v.y; a0[i + 2] = v.z; a0[i + 3] = v.w;
            }
            ull bp[4];
#pragma unroll
            for (int j = 0; j < 4; j++)
                bp[j] = *(const ull*)&Bs[kk][tn + 2 * j];
#pragma unroll
            for (int i = 0; i < 8; i++) {
                ull ap = pack2(a0[i]);
#pragma unroll
                for (int j = 0; j < 4; j++) ffma2(acc[i][j], ap, bp[j]);
            }
        }
        __syncthreads();
    }

    // epilogue: +bias, store in phase2 layout [t][n>>4][b][n&15]
    float bn_[8];
#pragma unroll
    for (int j = 0; j < 8; j++) bn_[j] = g_bpack[n0 + tn + j];
    const int nbase = n0 + tn;               // multiple of 8
#pragma unroll
    for (int i = 0; i < 8; i++) {
        float o[8];
#pragma unroll
        for (int j = 0; j < 4; j++) unpack2(acc[i][j], o[2 * j], o[2 * j + 1]);
#pragma unroll
        for (int j = 0; j < 8; j++) o[j] += bn_[j];
        const int m = m0 + tm + i;
        const int t = m >> 6, b = m & 63;
        size_t base = (((size_t)t * 128 + (nbase >> 4)) * 64 + b) * 16 + (nbase & 15);
        *(float4*)(g_Gx + base)     = make_float4(o[0], o[1], o[2], o[3]);
        *(float4*)(g_Gx + base + 4) = make_float4(o[4], o[5], o[6], o[7]);
    }
}

// ============================================================================
// Phase 2: persistent sequential LSTM. 128 CTAs x 256 threads, 1 CTA/SM.
// smem: sWh2 [16][512] ull (dup pairs, 64K) | sH [512][64] f32 (128K)
//       sPart [4][16][64] (16K) | sGx [64][16] (4K) | sHs [64][4] (1K)
// Warp w: rows r0=(w&1)*8..+8, k in [ (w>>1)*128, +128 ).
// Lane: batch pair (2*lane, 2*lane+1).
// ============================================================================
#define SM_WH   0
#define SM_H    65536
#define SM_PART (65536 + 131072)
#define SM_GX   (SM_PART + 4096 * 4)
#define SM_HS   (SM_GX + 1024 * 4)
#define SM_TOT  (SM_HS + 256 * 4)

__device__ __forceinline__ void grid_bar(unsigned target) {
    __threadfence();
    __syncthreads();
    if (threadIdx.x == 0) {
        atomicAdd(&g_bar, 1u);
        while (*(volatile unsigned*)&g_bar < target) {}
        __threadfence();
    }
    __syncthreads();
}

__global__ void __launch_bounds__(256, 1)
qlstm_seq(float* __restrict__ out) {
    extern __shared__ char smraw[];
    ull*   sWh2  = (ull*)(smraw + SM_WH);
    float* sH    = (float*)(smraw + SM_H);
    float* sPart = (float*)(smraw + SM_PART);
    float* sGx   = (float*)(smraw + SM_GX);
    float* sHs   = (float*)(smraw + SM_HS);

    const int tid = threadIdx.x;
    const int cta = blockIdx.x;

    // resident Wh slice as duplicated f32x2 pairs
    for (int i = tid; i < 16 * HID; i += 256)
        sWh2[i] = pack2(g_Whp[(size_t)cta * 16 * HID + i]);

    const int wrp = tid >> 5, lane = tid & 31;
    const int kq = wrp >> 1;              // k quarter 0..3
    const int r0 = (wrp & 1) * 8;         // row group 0 or 8
    const int k0 = kq * 128;
    const ull* wbase = sWh2 + r0 * HID + k0;
    const ull* sHu = (const ull*)sH;      // [512][32] pairs

    const int jl = tid >> 6, b = tid & 63;
    const int jg = cta * 4 + jl;
    float c_state = 0.0f, h_val = 0.0f;

    __syncthreads();

    for (int t = 0; t < SEQ; t++) {
        // ---- out store for step t-1 (overlaps with everything below) ----
        if (t > 0 && tid < 64) {
            float4 hv = *(float4*)&sHs[tid * 4];
            *(float4*)(out + (size_t)((t - 1) * BATCH + tid) * HID + cta * 4) = hv;
        }

        // ---- coalesced Gx stage: 4 KB for (t, cta) ----
        ((float4*)sGx)[tid] =
            ((const float4*)g_Gx)[((size_t)t * 128 + cta) * 256 + tid];

        if (t > 0) {
            // ---- h fill (uncached: written by other SMs this launch) ----
            const float4* src = (const float4*)(g_hT + ((t - 1) & 1) * (HID * BATCH));
#pragma unroll 4
            for (int i = tid; i < HID * BATCH / 4; i += 256)
                ((float4*)sH)[i] = __ldcv(src + i);
            __syncthreads();

            // ---- recurrent GEMM: 8 rows x 64 batches x 128 k per warp ----
            ull a[8];
#pragma unroll
            for (int r = 0; r < 8; r++) a[r] = 0ull;
#pragma unroll 2
            for (int kk = 0; kk < 128; kk += 2) {
                ull h0 = sHu[(k0 + kk) * 32 + lane];
                ull h1 = sHu[(k0 + kk + 1) * 32 + lane];
#pragma unroll
                for (int r = 0; r < 8; r++) {
                    ulonglong2 wv = *(const ulonglong2*)(wbase + r * HID + kk);
                    ffma2(a[r], wv.x, h0);
                    ffma2(a[r], wv.y, h1);
                }
            }
#pragma unroll
            for (int r = 0; r < 8; r++)
                *(ull*)&sPart[((kq * 16) + r0 + r) * 64 + 2 * lane] = a[r];
            __syncthreads();
        } else {
            __syncthreads();    // sGx visibility
        }

        // ---- elementwise: thread = (cell jl, batch b) ----
        float pre[4];
#pragma unroll
        for (int g = 0; g < 4; g++) {
            float s = sGx[b * 16 + jl * 4 + g];
            if (t > 0) {
#pragma unroll
                for (int q = 0; q < 4; q++)
                    s += sPart[(q * 16 + jl * 4 + g) * 64 + b];
            }
            pre[g] = s;
        }
        float fg = sigmoidf_(pre[0]);
        float ig = sigmoidf_(pre[1]);
        float gg = tanhf_(pre[2]);
        float og = sigmoidf_(pre[3]);
        c_state = fg * c_state + ig * gg;
        h_val = og * tanhf_(c_state);

        g_hT[(t & 1) * (HID * BATCH) + jg * BATCH + b] = h_val;  // coalesced
        sHs[b * 4 + jl] = h_val;                                 // stage for out

        grid_bar(128u * (unsigned)(t + 1));
    }

    // final step's outputs + hx/cx
    if (tid < 64) {
        float4 hv = *(float4*)&sHs[tid * 4];
        *(float4*)(out + (size_t)((SEQ - 1) * BATCH + tid) * HID + cta * 4) = hv;
    }
    const size_t off = (size_t)SEQ * BATCH * HID;
    out[off + (size_t)b * HID + jg] = h_val;
    out[off + (size_t)BATCH * HID + (size_t)b * HID + jg] = c_state;
}

// ============================================================================
extern "C" void kernel_launch(void* const* d_in, const int* in_sizes, int n_in,
                              void* d_out, int out_size) {
    const float* x  = (const float*)d_in[0];
    const float* Wf = (const float*)d_in[1];
    const float* bf = (const float*)d_in[2];
    const float* Wi = (const float*)d_in[3];
    const float* bi = (const float*)d_in[4];
    const float* Wg = (const float*)d_in[5];
    const float* bg = (const float*)d_in[6];
    const float* Wo = (const float*)d_in[7];
    const float* bo = (const float*)d_in[8];
    float* out = (float*)d_out;

    qlstm_reset<<<1, 32>>>();
    qlstm_pack<<<256, 256>>>(Wf, bf, Wi, bi, Wg, bg, Wo, bo);

    dim3 g1(NGATE / 128, M_TOT / 128);   // (16, 1024)
    qlstm_gemm_x<<<g1, 256>>>(x);

    cudaFuncSetAttribute(qlstm_seq, cudaFuncAttributeMaxDynamicSharedMemorySize,
                         SM_TOT);
    qlstm_seq<<<128, 256, SM_TOT>>>(out);
}